// round 3
// baseline (speedup 1.0000x reference)
#include <cuda_runtime.h>
#include <math.h>

#define BB 16
#define TT 8192
#define DD 128
#define CC 64
#define NN 128          // TT / CC

// Scratch: per-chunk weighted outer products (later overwritten in-place by the
// exclusive prefix state scan) and per-chunk decayed k-sums (later z-scan).
__device__ float g_W[(size_t)BB * NN * DD * DD];   // 134 MB
__device__ float g_ks[(size_t)BB * NN * DD];       // 1 MB

__device__ __forceinline__ float sigmoidf_(float x) { return 1.0f / (1.0f + expf(-x)); }

// ---------------------------------------------------------------------------
// Pass 1: per-chunk W_n[i][j] = sum_c lam^(C-1-c) k[c][i] v[c][j]
//         and ks_n[i] = sum_c lam^(C-1-c) k[c][i]
// grid = B*N blocks, 256 threads, 64 KB dynamic smem
// ---------------------------------------------------------------------------
__global__ void __launch_bounds__(256)
pass1_kernel(const float* __restrict__ k, const float* __restrict__ v,
             const float* __restrict__ logd)
{
    int b = blockIdx.x >> 7;
    int n = blockIdx.x & 127;
    extern __shared__ float sm[];
    float* kd = sm;            // [CC][DD] k premultiplied by chunk_decay
    float* vs = sm + CC * DD;  // [CC][DD]
    __shared__ float powl[CC + 1];
    int tid = threadIdx.x;
    if (tid == 0) {
        float lam = sigmoidf_(logd[0]);
        float p = 1.0f;
        for (int i = 0; i <= CC; i++) { powl[i] = p; p *= lam; }
    }
    __syncthreads();

    const float* kg = k + ((size_t)b * TT + (size_t)n * CC) * DD;
    const float* vg = v + ((size_t)b * TT + (size_t)n * CC) * DD;
    for (int idx = tid; idx < CC * DD; idx += 256) {
        int c = idx >> 7;
        kd[idx] = kg[idx] * powl[CC - 1 - c];
        vs[idx] = vg[idx];
    }
    __syncthreads();

    // ks
    if (tid < DD) {
        float s = 0.0f;
        for (int c = 0; c < CC; c++) s += kd[c * DD + tid];
        g_ks[((size_t)b * NN + n) * DD + tid] = s;
    }

    // W: 256 threads, each an 8x8 register tile of the 128x128 output
    int i0 = (tid >> 4) * 8, j0 = (tid & 15) * 8;
    float acc[8][8];
#pragma unroll
    for (int u = 0; u < 8; u++)
#pragma unroll
        for (int w = 0; w < 8; w++) acc[u][w] = 0.0f;

    for (int c = 0; c < CC; c++) {
        float4 a0 = *(const float4*)&kd[c * DD + i0];
        float4 a1 = *(const float4*)&kd[c * DD + i0 + 4];
        float4 b0 = *(const float4*)&vs[c * DD + j0];
        float4 b1 = *(const float4*)&vs[c * DD + j0 + 4];
        float av[8] = {a0.x, a0.y, a0.z, a0.w, a1.x, a1.y, a1.z, a1.w};
        float bv[8] = {b0.x, b0.y, b0.z, b0.w, b1.x, b1.y, b1.z, b1.w};
#pragma unroll
        for (int u = 0; u < 8; u++)
#pragma unroll
            for (int w = 0; w < 8; w++) acc[u][w] += av[u] * bv[w];
    }

    float* Wg = g_W + (size_t)blockIdx.x * DD * DD;  // blockIdx.x == b*NN + n
#pragma unroll
    for (int u = 0; u < 8; u++) {
        float4 o0 = {acc[u][0], acc[u][1], acc[u][2], acc[u][3]};
        float4 o1 = {acc[u][4], acc[u][5], acc[u][6], acc[u][7]};
        *(float4*)&Wg[(i0 + u) * DD + j0]     = o0;
        *(float4*)&Wg[(i0 + u) * DD + j0 + 4] = o1;
    }
}

// ---------------------------------------------------------------------------
// Pass 2a: in-place exclusive prefix scan of W -> state-before-chunk-n.
// One thread per (b,i,j). Also emits the final state if requested.
// ---------------------------------------------------------------------------
__global__ void __launch_bounds__(256)
pass2_state_kernel(const float* __restrict__ logd, float* __restrict__ out_state,
                   int write_final)
{
    int idx = blockIdx.x * 256 + threadIdx.x;   // < BB*DD*DD = 262144
    float lam = sigmoidf_(logd[0]);
    float dc = lam;
#pragma unroll
    for (int i = 0; i < 6; i++) dc *= dc;       // lam^64
    int b = idx >> 14;
    int e = idx & 16383;
    size_t base = (size_t)b * NN * DD * DD + e;
    float s = 0.0f;
    for (int n = 0; n < NN; n++) {
        size_t off = base + (size_t)n * DD * DD;
        float w = g_W[off];
        g_W[off] = s;
        s = dc * s + w;
    }
    if (write_final) out_state[idx] = s;
}

// Pass 2b: same scan for z (ks scratch). One thread per (b,i).
__global__ void __launch_bounds__(256)
pass2_z_kernel(const float* __restrict__ logd, float* __restrict__ out_z,
               int write_final)
{
    int idx = blockIdx.x * 256 + threadIdx.x;   // < BB*DD = 2048
    float lam = sigmoidf_(logd[0]);
    float dc = lam;
#pragma unroll
    for (int i = 0; i < 6; i++) dc *= dc;
    int b = idx >> 7;
    int e = idx & 127;
    size_t base = (size_t)b * NN * DD + e;
    float s = 0.0f;
    for (int n = 0; n < NN; n++) {
        size_t off = base + (size_t)n * DD;
        float w = g_ks[off];
        g_ks[off] = s;
        s = dc * s + w;
    }
    if (write_final) out_z[idx] = s;
}

// ---------------------------------------------------------------------------
// Pass 3: intra-chunk causal attention + cross-chunk state read + normalize.
// grid = B*N blocks, 256 threads.
// ---------------------------------------------------------------------------
#define QS 132   // padded row stride for q / k|v tiles (bank-conflict avoidance)
#define AS 68    // padded row stride for attn tile (float4-aligned, odd 16B phase)

__global__ void __launch_bounds__(256)
pass3_kernel(const float* __restrict__ q, const float* __restrict__ k,
             const float* __restrict__ v, const float* __restrict__ logd,
             float* __restrict__ out)
{
    int b = blockIdx.x >> 7;
    int n = blockIdx.x & 127;
    extern __shared__ float sm[];
    float* qs   = sm;                // [CC][QS]
    float* kv   = sm + CC * QS;      // [CC][QS], first k then overwritten by v
    float* attn = sm + 2 * CC * QS;  // [CC][AS]
    __shared__ float powl[CC + 1];
    __shared__ float iz[CC];
    __shared__ float cz[CC];
    int tid = threadIdx.x;
    if (tid == 0) {
        float lam = sigmoidf_(logd[0]);
        float p = 1.0f;
        for (int i = 0; i <= CC; i++) { powl[i] = p; p *= lam; }
    }
    __syncthreads();

    const float* qg = q + ((size_t)b * TT + (size_t)n * CC) * DD;
    const float* kg = k + ((size_t)b * TT + (size_t)n * CC) * DD;
    for (int idx = tid; idx < CC * DD; idx += 256) {
        int c = idx >> 7, d = idx & 127;
        qs[c * QS + d] = qg[idx];
        kv[c * QS + d] = kg[idx];
    }
    __syncthreads();

    // attn[c][j] = (j<=c) ? (q_c . k_j) * lam^(c-j) : 0
    {
        int c  = tid >> 2;
        int jo = tid & 3;
        float acc[16];
#pragma unroll
        for (int jj = 0; jj < 16; jj++) acc[jj] = 0.0f;
        for (int d4 = 0; d4 < DD / 4; d4++) {
            float4 qv = *(const float4*)&qs[c * QS + d4 * 4];
#pragma unroll
            for (int jj = 0; jj < 16; jj++) {
                int j = jo + jj * 4;
                float4 kk = *(const float4*)&kv[j * QS + d4 * 4];
                acc[jj] += qv.x * kk.x + qv.y * kk.y + qv.z * kk.z + qv.w * kk.w;
            }
        }
#pragma unroll
        for (int jj = 0; jj < 16; jj++) {
            int j = jo + jj * 4;
            attn[c * AS + j] = (j <= c) ? acc[jj] * powl[c - j] : 0.0f;
        }
    }
    __syncthreads();

    // row sums (clamped) and cross_z
    if (tid < CC) {
        int c = tid;
        float s = 0.0f;
        for (int j = 0; j <= c; j++) s += attn[c * AS + j];
        iz[c] = fmaxf(s, 1.0f);
        const float* zg = g_ks + ((size_t)b * NN + n) * DD;  // z before chunk n
        float cs = 0.0f;
        for (int i = 0; i < DD; i++) cs += zg[i] * qs[c * QS + i];
        cz[c] = cs * powl[c + 1];
    }
    __syncthreads();

    // overwrite k tile with v tile
    const float* vg = v + ((size_t)b * TT + (size_t)n * CC) * DD;
    for (int idx = tid; idx < CC * DD; idx += 256) {
        int c = idx >> 7, d = idx & 127;
        kv[c * QS + d] = vg[idx];
    }
    __syncthreads();

    // main accumulation: thread owns column d for 32 rows c = cg*32+r
    int d  = tid & 127;
    int cg = tid >> 7;
    float acc[32];
#pragma unroll
    for (int r = 0; r < 32; r++) acc[r] = 0.0f;

    const float* S = g_W + (size_t)blockIdx.x * DD * DD;  // state before chunk n
    // cross: acc[r] = sum_i q[c][i] * S[i][d]
    for (int i = 0; i < DD; i += 4) {
        float s0 = S[(i + 0) * DD + d];
        float s1 = S[(i + 1) * DD + d];
        float s2 = S[(i + 2) * DD + d];
        float s3 = S[(i + 3) * DD + d];
#pragma unroll
        for (int r = 0; r < 32; r++) {
            int c = cg * 32 + r;
            float4 q4 = *(const float4*)&qs[c * QS + i];
            acc[r] += q4.x * s0 + q4.y * s1 + q4.z * s2 + q4.w * s3;
        }
    }
#pragma unroll
    for (int r = 0; r < 32; r++) acc[r] *= powl[cg * 32 + r + 1];  // decay_q

    // intra: acc[r] += sum_j attn[c][j] * v[j][d]
    for (int j = 0; j < CC; j += 4) {
        float v0 = kv[(j + 0) * QS + d];
        float v1 = kv[(j + 1) * QS + d];
        float v2 = kv[(j + 2) * QS + d];
        float v3 = kv[(j + 3) * QS + d];
#pragma unroll
        for (int r = 0; r < 32; r++) {
            int c = cg * 32 + r;
            float4 a4 = *(const float4*)&attn[c * AS + j];
            acc[r] += a4.x * v0 + a4.y * v1 + a4.z * v2 + a4.w * v3;
        }
    }

    float* og = out + ((size_t)b * TT + (size_t)n * CC) * DD;
#pragma unroll
    for (int r = 0; r < 32; r++) {
        int c = cg * 32 + r;
        float tz = fmaxf(iz[c] + cz[c], 1.0f);
        og[c * DD + d] = acc[r] / tz;
    }
}

// ---------------------------------------------------------------------------
extern "C" void kernel_launch(void* const* d_in, const int* in_sizes, int n_in,
                              void* d_out, int out_size)
{
    const float* q    = (const float*)d_in[0];
    const float* k    = (const float*)d_in[1];
    const float* v    = (const float*)d_in[2];
    const float* logd = (const float*)d_in[3];

    float* out = (float*)d_out;
    const size_t OUT_MAIN = (size_t)BB * TT * DD;            // 16777216
    const size_t OUT_ST   = (size_t)BB * DD * DD;            // 262144
    const size_t OUT_Z    = (size_t)BB * DD;                 // 2048
    int write_final = ((size_t)out_size >= OUT_MAIN + OUT_ST + OUT_Z) ? 1 : 0;
    float* out_state = out + OUT_MAIN;
    float* out_z     = out_state + OUT_ST;

    static bool attr_set = false;
    if (!attr_set) {
        cudaFuncSetAttribute(pass1_kernel,
                             cudaFuncAttributeMaxDynamicSharedMemorySize,
                             CC * DD * 2 * sizeof(float));             // 64 KB
        cudaFuncSetAttribute(pass3_kernel,
                             cudaFuncAttributeMaxDynamicSharedMemorySize,
                             (2 * CC * QS + CC * AS) * sizeof(float)); // ~83 KB
        attr_set = true;
    }

    pass1_kernel<<<BB * NN, 256, CC * DD * 2 * sizeof(float)>>>(k, v, logd);
    pass2_state_kernel<<<(BB * DD * DD) / 256, 256>>>(logd, out_state, write_final);
    pass2_z_kernel<<<(BB * DD) / 256, 256>>>(logd, out_z, write_final);
    pass3_kernel<<<BB * NN, 256, (2 * CC * QS + CC * AS) * sizeof(float)>>>(
        q, k, v, logd, out);
}